// round 9
// baseline (speedup 1.0000x reference)
#include <cuda_runtime.h>
#include <cuda_bf16.h>
#include <cstdint>

// x (12,64,256,256) f32, w (64,64,3,3) f32, out (12,64,256,256) f32
// channel-shift (roll 32 over T*C=192) -> sign -> 3x3 same-pad conv, weights sign(w)*mean|w|[o]
// GEMM per tile: M=128 px, N=64, K=576, bf16 mma.sync m16n8k16 (exact for +-1 data).

#define NTILES 6144            // 12 images * 64 h-tiles * 8 w-tiles (tile = 4x32 px)
#define GRIDN  296             // persistent, 2 CTAs/SM

__device__ float g_scale[64];
__device__ uint2 g_Bpack[9 * 4 * 8 * 32];   // [tap][kt4][nt8][lane] -> (b0,b1) bf16 frags, 73728 B

// smem: B 73728 | A 26112 (204 px * 128B) | scale 256 = 100096 -> 2 CTAs/SM
#define SM_A     73728
#define SM_SC    99840
#define SMEM_DYN 100096

__device__ __forceinline__ uint32_t sign_bf16_bits(float x) {
    uint32_t u = __float_as_uint(x);
    uint32_t mag = u & 0x7FFFFFFFu;
    uint32_t s = (u >> 16) & 0x8000u;
    return mag ? (0x3F80u | s) : 0u;     // +-1.0 bf16, 0 if x==0
}

// -------------------- weight prep (unchanged from the 259us kernel) --------------------

__global__ void prep_scale_kernel(const float* __restrict__ w) {
    int o = blockIdx.x, tid = threadIdx.x;
    float s = 0.f;
    for (int i = tid; i < 576; i += 256) s += fabsf(w[o * 576 + i]);
    #pragma unroll
    for (int off = 16; off; off >>= 1) s += __shfl_down_sync(0xFFFFFFFFu, s, off);
    __shared__ float red[8];
    if ((tid & 31) == 0) red[tid >> 5] = s;
    __syncthreads();
    if (tid < 8) {
        float v = red[tid];
        #pragma unroll
        for (int off = 4; off; off >>= 1) v += __shfl_down_sync(0xFFu, v, off);
        if (tid == 0) g_scale[o] = v * (1.0f / 576.0f);
    }
}

__global__ void prep_weights_kernel(const float* __restrict__ w) {
    int tap = blockIdx.x;         // 0..8
    int kt  = blockIdx.y;         // 0..3
    int tid = threadIdx.x;        // 256
    int nt = tid >> 5, lane = tid & 31;
    int tig = lane & 3, g = lane >> 2;
    int o = nt * 8 + g;
    uint32_t e[4];
    #pragma unroll
    for (int j = 0; j < 4; j++) {
        int k = (j < 2) ? (2 * tig + j) : (2 * tig + 8 + (j - 2));
        int c = kt * 16 + k;
        e[j] = sign_bf16_bits(w[(o * 64 + c) * 9 + tap]);
    }
    g_Bpack[((tap * 4 + kt) * 8 + nt) * 32 + lane] = make_uint2(e[0] | (e[1] << 16), e[2] | (e[3] << 16));
}

// -------------------- vectorized tile loader --------------------
// A tile: 6 rows x 34 cols = 204 halo pixels, [pixel][64ch bf16], 128B rows,
// byte(pix, c) = pix*128 + ((2c) ^ ((pix&7)<<4))   (same physical layout as the 259us kernel)

__device__ __forceinline__ void store8(unsigned char* sA, int pix, int c,
                                       uint32_t lo, uint32_t hi) {
    uint32_t off = ((uint32_t)(2 * c)) ^ (((uint32_t)pix & 7u) << 4);
    *reinterpret_cast<uint2*>(sA + pix * 128 + off) = make_uint2(lo, hi);
}

__device__ __forceinline__ void load_tile(const float* __restrict__ x, unsigned char* sA,
                                          int tid, int b, int t, int h0, int w0) {
    const float* xb = x + (long)b * 12582912;
    // interior: 6 rows x 8 wgroups(4px) x 16 chgroups(4ch) = 768 tasks, 3 per thread
    #pragma unroll
    for (int rep = 0; rep < 3; rep++) {
        int tsk = tid + rep * 256;
        int chg = tsk & 15;
        int tmp = tsk >> 4;          // 0..47
        int wg = tmp & 7, pr = tmp >> 3;
        int h = h0 - 1 + pr;
        bool vh = (unsigned)h < 256u;
        int c = chg * 4;
        int flat = t * 64 + c - 32; if (flat < 0) flat += 192;
        float va[4][4];
        if (vh) {
            const float4* p = reinterpret_cast<const float4*>(
                xb + (long)flat * 65536 + (h * 256 + w0 + wg * 4));
            #pragma unroll
            for (int i = 0; i < 4; i++) {
                float4 v = __ldg(p + i * 16384);      // +1 channel plane
                va[i][0] = v.x; va[i][1] = v.y; va[i][2] = v.z; va[i][3] = v.w;
            }
        } else {
            #pragma unroll
            for (int i = 0; i < 4; i++) { va[i][0]=va[i][1]=va[i][2]=va[i][3]=0.f; }
        }
        int pix0 = pr * 34 + 1 + wg * 4;
        #pragma unroll
        for (int j = 0; j < 4; j++) {
            uint32_t lo = sign_bf16_bits(va[0][j]) | (sign_bf16_bits(va[1][j]) << 16);
            uint32_t hi = sign_bf16_bits(va[2][j]) | (sign_bf16_bits(va[3][j]) << 16);
            store8(sA, pix0 + j, c, lo, hi);
        }
    }
    // halo columns pc=0 (w0-1) and pc=33 (w0+32): 6 rows x 2 sides x 16 chgroups = 192 tasks
    if (tid < 192) {
        int chg = tid & 15;
        int tmp = tid >> 4;          // 0..11
        int side = tmp & 1, pr = tmp >> 1;
        int h = h0 - 1 + pr;
        int w = w0 - 1 + side * 33;
        bool valid = ((unsigned)h < 256u) && ((unsigned)w < 256u);
        int c = chg * 4;
        int flat = t * 64 + c - 32; if (flat < 0) flat += 192;
        float s0 = 0.f, s1 = 0.f, s2 = 0.f, s3 = 0.f;
        if (valid) {
            const float* p = xb + (long)flat * 65536 + (h * 256 + w);
            s0 = __ldg(p); s1 = __ldg(p + 65536); s2 = __ldg(p + 131072); s3 = __ldg(p + 196608);
        }
        uint32_t lo = sign_bf16_bits(s0) | (sign_bf16_bits(s1) << 16);
        uint32_t hi = sign_bf16_bits(s2) | (sign_bf16_bits(s3) << 16);
        store8(sA, pr * 34 + side * 33, c, lo, hi);
    }
}

// -------------------- persistent fused kernel --------------------

__global__ void __launch_bounds__(256, 2)
conv_kernel(const float* __restrict__ x, float* __restrict__ out) {
    extern __shared__ unsigned char smem[];
    uint2* sB = reinterpret_cast<uint2*>(smem);
    unsigned char* sA = smem + SM_A;
    float* sScale = reinterpret_cast<float*>(smem + SM_SC);

    const int tid = threadIdx.x;
    const int bid = blockIdx.x;

    // stage B once per CTA (4608 uint4) + scales
    {
        const uint4* src = reinterpret_cast<const uint4*>(g_Bpack);
        uint4* dst = reinterpret_cast<uint4*>(smem);
        #pragma unroll
        for (int k = 0; k < 18; k++) dst[tid + k * 256] = src[tid + k * 256];
    }
    if (tid < 64) sScale[tid] = g_scale[tid];

    const int warp = tid >> 5, lane = tid & 31;
    const int ph  = warp >> 1;               // output tile row 0..3
    const int pw0 = (warp & 1) * 16;         // output tile col base 0/16
    const int tig = lane & 3, g = lane >> 2;
    const int mrow = lane & 15;
    const int khalf = lane >> 4;

    const uint32_t sA_base = (uint32_t)__cvta_generic_to_shared(sA);
    const int n_my = (NTILES - 1 - bid) / GRIDN + 1;

    for (int it = 0; it < n_my; it++) {
        const int tl = bid + it * GRIDN;
        const int bt = tl >> 9, rem = tl & 511;
        const int h0 = (rem >> 3) * 4, w0 = (rem & 7) * 32;

        load_tile(x, sA, tid, bt / 3, bt % 3, h0, w0);
        __syncthreads();

        // ---- mainloop (identical to the 259us kernel) ----
        float acc[8][4];
        #pragma unroll
        for (int nt = 0; nt < 8; nt++) { acc[nt][0]=acc[nt][1]=acc[nt][2]=acc[nt][3]=0.f; }

        #pragma unroll
        for (int tap = 0; tap < 9; tap++) {
            const int kh = tap / 3, kw = tap - kh * 3;
            const int pix = (ph + kh) * 34 + pw0 + kw + mrow;
            const uint32_t pix_sw = ((uint32_t)pix & 7u) << 4;
            #pragma unroll
            for (int kt = 0; kt < 4; kt++) {
                uint32_t a0, a1, a2, a3;
                uint32_t addr = sA_base + (uint32_t)pix * 128u
                              + (((uint32_t)(kt * 32 + khalf * 16)) ^ pix_sw);
                asm volatile("ldmatrix.sync.aligned.x4.m8n8.shared.b16 {%0,%1,%2,%3}, [%4];"
                             : "=r"(a0), "=r"(a1), "=r"(a2), "=r"(a3) : "r"(addr));
                #pragma unroll
                for (int nt = 0; nt < 8; nt++) {
                    uint2 bb = sB[((tap * 4 + kt) * 8 + nt) * 32 + lane];
                    asm volatile(
                        "mma.sync.aligned.m16n8k16.row.col.f32.bf16.bf16.f32 "
                        "{%0,%1,%2,%3}, {%4,%5,%6,%7}, {%8,%9}, {%0,%1,%2,%3};"
                        : "+f"(acc[nt][0]), "+f"(acc[nt][1]), "+f"(acc[nt][2]), "+f"(acc[nt][3])
                        : "r"(a0), "r"(a1), "r"(a2), "r"(a3), "r"(bb.x), "r"(bb.y));
                }
            }
        }

        // ---- epilogue ----
        {
            const int hh = h0 + ph;
            const int wb = w0 + pw0 + g;
            #pragma unroll
            for (int nt = 0; nt < 8; nt++) {
                int o0 = nt * 8 + 2 * tig;
                float s0 = sScale[o0], s1 = sScale[o0 + 1];
                long base0 = ((long)(bt * 64 + o0) << 16) + (hh << 8) + wb;
                long base1 = base0 + 65536;
                out[base0]     = s0 * acc[nt][0];
                out[base1]     = s1 * acc[nt][1];
                out[base0 + 8] = s0 * acc[nt][2];
                out[base1 + 8] = s1 * acc[nt][3];
            }
        }
        __syncthreads();
    }
}

// -------------------- launch --------------------

extern "C" void kernel_launch(void* const* d_in, const int* in_sizes, int n_in,
                              void* d_out, int out_size) {
    const float* x = (const float*)d_in[0];
    const float* w = (const float*)d_in[1];
    float* out = (float*)d_out;

    cudaFuncSetAttribute(conv_kernel, cudaFuncAttributeMaxDynamicSharedMemorySize, SMEM_DYN);

    prep_scale_kernel<<<64, 256>>>(w);
    prep_weights_kernel<<<dim3(9, 4, 1), 256>>>(w);
    conv_kernel<<<GRIDN, 256, SMEM_DYN>>>(x, out);
}

// round 10
// speedup vs baseline: 1.4824x; 1.4824x over previous
#include <cuda_runtime.h>
#include <cuda_bf16.h>
#include <cstdint>

// x (12,64,256,256) f32, w (64,64,3,3) f32, out (12,64,256,256) f32
// channel-shift (roll 32 over T*C=192) -> sign -> 3x3 same-pad conv, weights sign(w)*mean|w|[o]
// GEMM per tile: M=128 px (4x32), N=64, K=576, bf16 mma.sync m16n8k16 (exact for +-1 data).
// One tile per CTA (grid 6144) for maximal inter-CTA load/compute overlap; vectorized loader.

__device__ float g_scale[64];
__device__ uint2 g_Bpack[9 * 4 * 8 * 32];   // [tap][kt4][nt8][lane] -> (b0,b1) bf16 frags, 73728 B

// smem: B 73728 | A 26112 (204 px * 128B) | scale 256 = 100096 -> 2 CTAs/SM
#define SM_A     73728
#define SM_SC    99840
#define SMEM_DYN 100096

__device__ __forceinline__ uint32_t sign_bf16_bits(float x) {
    uint32_t u = __float_as_uint(x);
    uint32_t mag = u & 0x7FFFFFFFu;
    uint32_t s = (u >> 16) & 0x8000u;
    return mag ? (0x3F80u | s) : 0u;     // +-1.0 bf16, 0 if x==0
}

// -------------------- weight prep --------------------

__global__ void prep_scale_kernel(const float* __restrict__ w) {
    int o = blockIdx.x, tid = threadIdx.x;
    float s = 0.f;
    for (int i = tid; i < 576; i += 256) s += fabsf(w[o * 576 + i]);
    #pragma unroll
    for (int off = 16; off; off >>= 1) s += __shfl_down_sync(0xFFFFFFFFu, s, off);
    __shared__ float red[8];
    if ((tid & 31) == 0) red[tid >> 5] = s;
    __syncthreads();
    if (tid < 8) {
        float v = red[tid];
        #pragma unroll
        for (int off = 4; off; off >>= 1) v += __shfl_down_sync(0xFFu, v, off);
        if (tid == 0) g_scale[o] = v * (1.0f / 576.0f);
    }
}

__global__ void prep_weights_kernel(const float* __restrict__ w) {
    int tap = blockIdx.x;         // 0..8
    int kt  = blockIdx.y;         // 0..3
    int tid = threadIdx.x;        // 256
    int nt = tid >> 5, lane = tid & 31;
    int tig = lane & 3, g = lane >> 2;
    int o = nt * 8 + g;
    uint32_t e[4];
    #pragma unroll
    for (int j = 0; j < 4; j++) {
        int k = (j < 2) ? (2 * tig + j) : (2 * tig + 8 + (j - 2));
        int c = kt * 16 + k;
        e[j] = sign_bf16_bits(w[(o * 64 + c) * 9 + tap]);
    }
    g_Bpack[((tap * 4 + kt) * 8 + nt) * 32 + lane] = make_uint2(e[0] | (e[1] << 16), e[2] | (e[3] << 16));
}

// -------------------- vectorized tile loader --------------------
// A tile: 6 rows x 34 cols = 204 halo pixels, [pixel][64ch bf16], 128B rows,
// byte(pix, c) = pix*128 + ((2c) ^ ((pix&7)<<4))

__device__ __forceinline__ void store8(unsigned char* sA, int pix, int c,
                                       uint32_t lo, uint32_t hi) {
    uint32_t off = ((uint32_t)(2 * c)) ^ (((uint32_t)pix & 7u) << 4);
    *reinterpret_cast<uint2*>(sA + pix * 128 + off) = make_uint2(lo, hi);
}

__device__ __forceinline__ void load_tile(const float* __restrict__ x, unsigned char* sA,
                                          int tid, int b, int t, int h0, int w0) {
    const float* xb = x + (long)b * 12582912;
    // interior: 6 rows x 8 wgroups(4px) x 16 chgroups(4ch) = 768 tasks, 3 per thread
    #pragma unroll
    for (int rep = 0; rep < 3; rep++) {
        int tsk = tid + rep * 256;
        int chg = tsk & 15;
        int tmp = tsk >> 4;          // 0..47
        int wg = tmp & 7, pr = tmp >> 3;
        int h = h0 - 1 + pr;
        bool vh = (unsigned)h < 256u;
        int c = chg * 4;
        int flat = t * 64 + c - 32; if (flat < 0) flat += 192;
        float va[4][4];
        if (vh) {
            const float4* p = reinterpret_cast<const float4*>(
                xb + (long)flat * 65536 + (h * 256 + w0 + wg * 4));
            #pragma unroll
            for (int i = 0; i < 4; i++) {
                float4 v = __ldg(p + i * 16384);      // +1 channel plane
                va[i][0] = v.x; va[i][1] = v.y; va[i][2] = v.z; va[i][3] = v.w;
            }
        } else {
            #pragma unroll
            for (int i = 0; i < 4; i++) { va[i][0]=va[i][1]=va[i][2]=va[i][3]=0.f; }
        }
        int pix0 = pr * 34 + 1 + wg * 4;
        #pragma unroll
        for (int j = 0; j < 4; j++) {
            uint32_t lo = sign_bf16_bits(va[0][j]) | (sign_bf16_bits(va[1][j]) << 16);
            uint32_t hi = sign_bf16_bits(va[2][j]) | (sign_bf16_bits(va[3][j]) << 16);
            store8(sA, pix0 + j, c, lo, hi);
        }
    }
    // halo columns pc=0 (w0-1) and pc=33 (w0+32): 6 rows x 2 sides x 16 chgroups = 192 tasks
    if (tid < 192) {
        int chg = tid & 15;
        int tmp = tid >> 4;          // 0..11
        int side = tmp & 1, pr = tmp >> 1;
        int h = h0 - 1 + pr;
        int w = w0 - 1 + side * 33;
        bool valid = ((unsigned)h < 256u) && ((unsigned)w < 256u);
        int c = chg * 4;
        int flat = t * 64 + c - 32; if (flat < 0) flat += 192;
        float s0 = 0.f, s1 = 0.f, s2 = 0.f, s3 = 0.f;
        if (valid) {
            const float* p = xb + (long)flat * 65536 + (h * 256 + w);
            s0 = __ldg(p); s1 = __ldg(p + 65536); s2 = __ldg(p + 131072); s3 = __ldg(p + 196608);
        }
        uint32_t lo = sign_bf16_bits(s0) | (sign_bf16_bits(s1) << 16);
        uint32_t hi = sign_bf16_bits(s2) | (sign_bf16_bits(s3) << 16);
        store8(sA, pr * 34 + side * 33, c, lo, hi);
    }
}

// -------------------- fused conv kernel: one tile per CTA --------------------

__global__ void __launch_bounds__(256, 2)
conv_kernel(const float* __restrict__ x, float* __restrict__ out) {
    extern __shared__ unsigned char smem[];
    uint2* sB = reinterpret_cast<uint2*>(smem);
    unsigned char* sA = smem + SM_A;
    float* sScale = reinterpret_cast<float*>(smem + SM_SC);

    const int tid = threadIdx.x;
    const int bt = blockIdx.z;                 // 0..11
    const int h0 = blockIdx.y * 4;
    const int w0 = blockIdx.x * 32;
    const int b = bt / 3, t = bt % 3;

    // stage B (4608 uint4) + scales
    {
        const uint4* src = reinterpret_cast<const uint4*>(g_Bpack);
        uint4* dst = reinterpret_cast<uint4*>(smem);
        #pragma unroll
        for (int k = 0; k < 18; k++) dst[tid + k * 256] = src[tid + k * 256];
    }
    if (tid < 64) sScale[tid] = g_scale[tid];

    // vectorized A tile load
    load_tile(x, sA, tid, b, t, h0, w0);
    __syncthreads();

    // ---- mainloop (identical to the 259us kernel) ----
    const int warp = tid >> 5, lane = tid & 31;
    const int ph  = warp >> 1;               // output tile row 0..3
    const int pw0 = (warp & 1) * 16;         // output tile col base 0/16
    const int tig = lane & 3, g = lane >> 2;
    const int mrow = lane & 15;
    const int khalf = lane >> 4;

    const uint32_t sA_base = (uint32_t)__cvta_generic_to_shared(sA);

    float acc[8][4];
    #pragma unroll
    for (int nt = 0; nt < 8; nt++) { acc[nt][0]=acc[nt][1]=acc[nt][2]=acc[nt][3]=0.f; }

    #pragma unroll
    for (int tap = 0; tap < 9; tap++) {
        const int kh = tap / 3, kw = tap - kh * 3;
        const int pix = (ph + kh) * 34 + pw0 + kw + mrow;
        const uint32_t pix_sw = ((uint32_t)pix & 7u) << 4;
        #pragma unroll
        for (int kt = 0; kt < 4; kt++) {
            uint32_t a0, a1, a2, a3;
            uint32_t addr = sA_base + (uint32_t)pix * 128u
                          + (((uint32_t)(kt * 32 + khalf * 16)) ^ pix_sw);
            asm volatile("ldmatrix.sync.aligned.x4.m8n8.shared.b16 {%0,%1,%2,%3}, [%4];"
                         : "=r"(a0), "=r"(a1), "=r"(a2), "=r"(a3) : "r"(addr));
            #pragma unroll
            for (int nt = 0; nt < 8; nt++) {
                uint2 bb = sB[((tap * 4 + kt) * 8 + nt) * 32 + lane];
                asm volatile(
                    "mma.sync.aligned.m16n8k16.row.col.f32.bf16.bf16.f32 "
                    "{%0,%1,%2,%3}, {%4,%5,%6,%7}, {%8,%9}, {%0,%1,%2,%3};"
                    : "+f"(acc[nt][0]), "+f"(acc[nt][1]), "+f"(acc[nt][2]), "+f"(acc[nt][3])
                    : "r"(a0), "r"(a1), "r"(a2), "r"(a3), "r"(bb.x), "r"(bb.y));
            }
        }
    }

    // ---- epilogue ----
    const int hh = h0 + ph;
    const int wb = w0 + pw0 + g;
    #pragma unroll
    for (int nt = 0; nt < 8; nt++) {
        int o0 = nt * 8 + 2 * tig;
        float s0 = sScale[o0], s1 = sScale[o0 + 1];
        long base0 = ((long)(bt * 64 + o0) << 16) + (hh << 8) + wb;
        long base1 = base0 + 65536;
        out[base0]     = s0 * acc[nt][0];
        out[base1]     = s1 * acc[nt][1];
        out[base0 + 8] = s0 * acc[nt][2];
        out[base1 + 8] = s1 * acc[nt][3];
    }
}

// -------------------- launch --------------------

extern "C" void kernel_launch(void* const* d_in, const int* in_sizes, int n_in,
                              void* d_out, int out_size) {
    const float* x = (const float*)d_in[0];
    const float* w = (const float*)d_in[1];
    float* out = (float*)d_out;

    cudaFuncSetAttribute(conv_kernel, cudaFuncAttributeMaxDynamicSharedMemorySize, SMEM_DYN);

    prep_scale_kernel<<<64, 256>>>(w);
    prep_weights_kernel<<<dim3(9, 4, 1), 256>>>(w);
    conv_kernel<<<dim3(8, 64, 12), 256, SMEM_DYN>>>(x, out);
}

// round 11
// speedup vs baseline: 1.8399x; 1.2412x over previous
#include <cuda_runtime.h>
#include <cuda_bf16.h>
#include <cstdint>

// x (12,64,256,256) f32, w (64,64,3,3) f32, out (12,64,256,256) f32
// channel-shift (roll 32 over T*C=192) -> sign -> 3x3 same-pad conv, weights sign(w)*mean|w|[o]
// Persistent kernel: 148 CTAs x 512 thr, tile M=256 px (8x32), N=64, K=576,
// bf16 mma.sync m16n8k16 (exact for +-1 data), double-buffered A, B staged once.

#define NT      3072           // 12 images * 32 h-tiles * 8 w-tiles (tile = 8x32 px)
#define GRIDN   148
#define THREADS 512

__device__ float g_scale[64];
__device__ uint2 g_Bpack[9 * 4 * 8 * 32];   // [tap][kt4][nt8][lane] -> (b0,b1) bf16 frags, 73728 B

// smem: B 73728 | A0 43520 (340 px * 128B) | A1 43520 | scale 256 = 161024
#define SM_A0    73728
#define SM_A1    117248
#define SM_SC    160768
#define SMEM_DYN 161024

__device__ __forceinline__ uint32_t sign_bf16_bits(float x) {
    uint32_t u = __float_as_uint(x);
    uint32_t mag = u & 0x7FFFFFFFu;
    uint32_t s = (u >> 16) & 0x8000u;
    return mag ? (0x3F80u | s) : 0u;     // +-1.0 bf16, 0 if x==0
}

// -------------------- weight prep (validated) --------------------

__global__ void prep_scale_kernel(const float* __restrict__ w) {
    int o = blockIdx.x, tid = threadIdx.x;
    float s = 0.f;
    for (int i = tid; i < 576; i += 256) s += fabsf(w[o * 576 + i]);
    #pragma unroll
    for (int off = 16; off; off >>= 1) s += __shfl_down_sync(0xFFFFFFFFu, s, off);
    __shared__ float red[8];
    if ((tid & 31) == 0) red[tid >> 5] = s;
    __syncthreads();
    if (tid < 8) {
        float v = red[tid];
        #pragma unroll
        for (int off = 4; off; off >>= 1) v += __shfl_down_sync(0xFFu, v, off);
        if (tid == 0) g_scale[o] = v * (1.0f / 576.0f);
    }
}

__global__ void prep_weights_kernel(const float* __restrict__ w) {
    int tap = blockIdx.x;         // 0..8
    int kt  = blockIdx.y;         // 0..3
    int tid = threadIdx.x;        // 256
    int nt = tid >> 5, lane = tid & 31;
    int tig = lane & 3, g = lane >> 2;
    int o = nt * 8 + g;
    uint32_t e[4];
    #pragma unroll
    for (int j = 0; j < 4; j++) {
        int k = (j < 2) ? (2 * tig + j) : (2 * tig + 8 + (j - 2));
        int c = kt * 16 + k;
        e[j] = sign_bf16_bits(w[(o * 64 + c) * 9 + tap]);
    }
    g_Bpack[((tap * 4 + kt) * 8 + nt) * 32 + lane] = make_uint2(e[0] | (e[1] << 16), e[2] | (e[3] << 16));
}

// -------------------- tile loader (scalar coalesced, half-split) --------------------
// A tile: 10 rows x 34 cols = 340 halo pixels, [pixel][64ch bf16], 128B rows,
// byte(pix, c) = pix*128 + ((2c) ^ ((pix&7)<<4))
// 680 tasks: (pixel, 32-channel half); lanes = consecutive tasks -> coalesced pixel runs.

__device__ __forceinline__ void load_tile(const float* __restrict__ x, unsigned char* sA,
                                          int tid, int b, int t, int h0, int w0) {
    #pragma unroll
    for (int rep = 0; rep < 2; rep++) {
        int task = tid + rep * 512;
        if (task >= 680) break;
        int half = task & 1;
        int pix = task >> 1;
        int pr = pix / 34, pc = pix - pr * 34;
        int h = h0 - 1 + pr, ww = w0 - 1 + pc;
        bool valid = ((unsigned)h < 256u) && ((unsigned)ww < 256u);
        int fb = t * 64 + half * 32 - 32; if (fb < 0) fb += 192;   // contiguous 32-ch block
        const float* xb = x + (long)(b * 192 + fb) * 65536 + (h * 256 + ww);
        uint32_t wd[16];
        #pragma unroll
        for (int q = 0; q < 16; q++) {
            uint32_t lo = 0, hi = 0;
            if (valid) {
                lo = sign_bf16_bits(__ldg(xb + ((long)(2 * q) << 16)));
                hi = sign_bf16_bits(__ldg(xb + ((long)(2 * q + 1) << 16)));
            }
            wd[q] = lo | (hi << 16);
        }
        unsigned char* row = sA + pix * 128;
        uint32_t pw7 = (uint32_t)(pix & 7);
        #pragma unroll
        for (int j = 0; j < 4; j++) {
            uint32_t chunk = ((uint32_t)(half * 4 + j)) ^ pw7;
            *reinterpret_cast<uint4*>(row + (chunk << 4)) =
                make_uint4(wd[4 * j], wd[4 * j + 1], wd[4 * j + 2], wd[4 * j + 3]);
        }
    }
}

// -------------------- persistent fused kernel --------------------

__global__ void __launch_bounds__(THREADS, 1)
conv_kernel(const float* __restrict__ x, float* __restrict__ out) {
    extern __shared__ unsigned char smem[];
    uint2* sB = reinterpret_cast<uint2*>(smem);
    float* sScale = reinterpret_cast<float*>(smem + SM_SC);

    const int tid = threadIdx.x;
    const int bid = blockIdx.x;

    // stage B once (4608 uint4 / 512 thr = 9 each) + scales
    {
        const uint4* src = reinterpret_cast<const uint4*>(g_Bpack);
        uint4* dst = reinterpret_cast<uint4*>(smem);
        #pragma unroll
        for (int k = 0; k < 9; k++) dst[tid + k * 512] = src[tid + k * 512];
    }
    if (tid < 64) sScale[tid] = g_scale[tid];

    const int warp = tid >> 5, lane = tid & 31;
    const int ph  = warp >> 1;               // tile row 0..7
    const int pw0 = (warp & 1) * 16;         // tile col base 0/16
    const int tig = lane & 3, g = lane >> 2;
    const int mrow = lane & 15;
    const int khalf = lane >> 4;

    const int n_my = (NT - 1 - bid) / GRIDN + 1;

    // preload tile 0
    {
        int tl = bid;
        int bt = tl >> 8, rem = tl & 255;
        load_tile(x, smem + SM_A0, tid, bt / 3, bt % 3, (rem >> 3) * 8, (rem & 7) * 32);
    }
    __syncthreads();

    for (int it = 0; it < n_my; it++) {
        const int tl = bid + it * GRIDN;
        const int bt = tl >> 8, rem = tl & 255;
        const int h0 = (rem >> 3) * 8, w0 = (rem & 7) * 32;

        // issue next tile's loads into the other buffer (overlaps mainloop below)
        if (it + 1 < n_my) {
            int tl2 = bid + (it + 1) * GRIDN;
            int bt2 = tl2 >> 8, rem2 = tl2 & 255;
            load_tile(x, smem + (((it + 1) & 1) ? SM_A1 : SM_A0), tid,
                      bt2 / 3, bt2 % 3, (rem2 >> 3) * 8, (rem2 & 7) * 32);
        }

        // ---- mainloop on current buffer ----
        const unsigned char* sA = smem + ((it & 1) ? SM_A1 : SM_A0);
        const uint32_t sA_base = (uint32_t)__cvta_generic_to_shared(sA);

        float acc[8][4];
        #pragma unroll
        for (int nt = 0; nt < 8; nt++) { acc[nt][0]=acc[nt][1]=acc[nt][2]=acc[nt][3]=0.f; }

        #pragma unroll
        for (int tap = 0; tap < 9; tap++) {
            const int kh = tap / 3, kw = tap - kh * 3;
            const int pix = (ph + kh) * 34 + pw0 + kw + mrow;
            const uint32_t pix_sw = ((uint32_t)pix & 7u) << 4;
            #pragma unroll
            for (int kt = 0; kt < 4; kt++) {
                uint32_t a0, a1, a2, a3;
                uint32_t addr = sA_base + (uint32_t)pix * 128u
                              + (((uint32_t)(kt * 32 + khalf * 16)) ^ pix_sw);
                asm volatile("ldmatrix.sync.aligned.x4.m8n8.shared.b16 {%0,%1,%2,%3}, [%4];"
                             : "=r"(a0), "=r"(a1), "=r"(a2), "=r"(a3) : "r"(addr));
                #pragma unroll
                for (int nt = 0; nt < 8; nt++) {
                    uint2 bb = sB[((tap * 4 + kt) * 8 + nt) * 32 + lane];
                    asm volatile(
                        "mma.sync.aligned.m16n8k16.row.col.f32.bf16.bf16.f32 "
                        "{%0,%1,%2,%3}, {%4,%5,%6,%7}, {%8,%9}, {%0,%1,%2,%3};"
                        : "+f"(acc[nt][0]), "+f"(acc[nt][1]), "+f"(acc[nt][2]), "+f"(acc[nt][3])
                        : "r"(a0), "r"(a1), "r"(a2), "r"(a3), "r"(bb.x), "r"(bb.y));
                }
            }
        }

        // ---- epilogue ----
        {
            const int hh = h0 + ph;
            const int wb = w0 + pw0 + g;
            #pragma unroll
            for (int nt = 0; nt < 8; nt++) {
                int o0 = nt * 8 + 2 * tig;
                float s0 = sScale[o0], s1 = sScale[o0 + 1];
                long base0 = ((long)(bt * 64 + o0) << 16) + (hh << 8) + wb;
                long base1 = base0 + 65536;
                out[base0]     = s0 * acc[nt][0];
                out[base1]     = s1 * acc[nt][1];
                out[base0 + 8] = s0 * acc[nt][2];
                out[base1 + 8] = s1 * acc[nt][3];
            }
        }
        __syncthreads();   // next buffer's STS visible; safe to overwrite current next iter
    }
}

// -------------------- launch --------------------

extern "C" void kernel_launch(void* const* d_in, const int* in_sizes, int n_in,
                              void* d_out, int out_size) {
    const float* x = (const float*)d_in[0];
    const float* w = (const float*)d_in[1];
    float* out = (float*)d_out;

    cudaFuncSetAttribute(conv_kernel, cudaFuncAttributeMaxDynamicSharedMemorySize, SMEM_DYN);

    prep_scale_kernel<<<64, 256>>>(w);
    prep_weights_kernel<<<dim3(9, 4, 1), 256>>>(w);
    conv_kernel<<<GRIDN, THREADS, SMEM_DYN>>>(x, out);
}